// round 5
// baseline (speedup 1.0000x reference)
#include <cuda_runtime.h>
#include <cuda_bf16.h>

#define F_IN   128
#define F_OUT  64
#define N_NODES_MAX 100000
#define E_MAX       1600000

#define TILE_M        128
#define GEMM_THREADS  128
#define XS_STRIDE     129   // pad to kill bank conflicts on Xs[row][k] reads

// smem: Xs[TILE_M][XS_STRIDE] + Ws[F_IN][F_OUT]
#define SMEM_FLOATS   (TILE_M * XS_STRIDE + F_IN * F_OUT)
#define SMEM_BYTES    (SMEM_FLOATS * 4)

// ---- device scratch (no allocations allowed) ----
__device__ float g_support[(size_t)N_NODES_MAX * F_OUT];   // 25.6 MB
__device__ int   g_offsets[N_NODES_MAX];                   // CSR row starts
__device__ int   g_cursor [N_NODES_MAX];                   // becomes row ends after scatter
__device__ int2  g_sorted [E_MAX];                         // {src, bits(ew)} sorted by dst

// packed f32x2 FMA: d = a*b + d  (sm_100+; ptxas never emits this from C++).
// Explicit 4-operand form (no "+l" tied constraint -> avoids cicc ICE).
__device__ __forceinline__ void fma2(unsigned long long& d,
                                     unsigned long long a,
                                     unsigned long long b)
{
    unsigned long long r;
    asm volatile("fma.rn.f32x2 %0, %1, %2, %3;"
                 : "=l"(r) : "l"(a), "l"(b), "l"(d));
    d = r;
}
__device__ __forceinline__ unsigned long long pack2(float lo, float hi)
{
    unsigned long long r;
    asm("mov.b64 %0, {%1, %2};" : "=l"(r) : "f"(lo), "f"(hi));
    return r;
}

// ---------------------------------------------------------------------------
// Kernel 1: support = X @ W   (128x64 tile / 128 threads; 8x8 per thread,
// accumulators packed pairwise -> fma.rn.f32x2)
// ---------------------------------------------------------------------------
__global__ void gemm_support_kernel(const float* __restrict__ X,
                                    const float* __restrict__ W,
                                    int n_rows)
{
    extern __shared__ float smem[];
    float* Xs = smem;                          // [TILE_M][XS_STRIDE]
    float* Ws = smem + TILE_M * XS_STRIDE;     // [F_IN][F_OUT] row-major

    const int tid      = threadIdx.x;
    const int row_base = blockIdx.x * TILE_M;

    // stage W (8192 floats = 2048 float4)
    {
        const float4* W4  = (const float4*)W;
        float4*       Ws4 = (float4*)Ws;
        #pragma unroll
        for (int i = 0; i < (F_IN * F_OUT / 4) / GEMM_THREADS; i++)
            Ws4[tid + i * GEMM_THREADS] = W4[tid + i * GEMM_THREADS];
    }

    // stage X tile
    #pragma unroll
    for (int i = 0; i < (TILE_M * F_IN / 4) / GEMM_THREADS; i++) {
        int idx = tid + i * GEMM_THREADS;
        int r   = idx >> 5;
        int kq  = idx & 31;
        float4 v = make_float4(0.f, 0.f, 0.f, 0.f);
        int gr = row_base + r;
        if (gr < n_rows)
            v = ((const float4*)(X + (size_t)gr * F_IN))[kq];
        float* dstp = &Xs[r * XS_STRIDE + kq * 4];
        dstp[0] = v.x; dstp[1] = v.y; dstp[2] = v.z; dstp[3] = v.w;
    }
    __syncthreads();

    const int tx = tid & 7;     // col group: cols tx*8 .. tx*8+7
    const int ty = tid >> 3;    // row group: rows ty*8 .. ty*8+7
    const int c0 = tx * 8;
    const int r0 = ty * 8;

    unsigned long long acc2[8][4];
    #pragma unroll
    for (int i = 0; i < 8; i++)
        #pragma unroll
        for (int j = 0; j < 4; j++)
            acc2[i][j] = 0ull;

    #pragma unroll 4
    for (int k = 0; k < F_IN; k++) {
        unsigned long long xv2[8];
        #pragma unroll
        for (int i = 0; i < 8; i++) {
            float xv = Xs[(r0 + i) * XS_STRIDE + k];
            xv2[i] = pack2(xv, xv);
        }
        // W pairs: adjacent cols -> direct 64-bit shared loads
        const unsigned long long* wrow =
            (const unsigned long long*)&Ws[k * F_OUT + c0];
        unsigned long long wv2[4];
        #pragma unroll
        for (int j = 0; j < 4; j++) wv2[j] = wrow[j];

        #pragma unroll
        for (int i = 0; i < 8; i++)
            #pragma unroll
            for (int j = 0; j < 4; j++)
                fma2(acc2[i][j], xv2[i], wv2[j]);
    }

    // write support tile
    #pragma unroll
    for (int i = 0; i < 8; i++) {
        int gr = row_base + r0 + i;
        if (gr < n_rows) {
            float2 p0 = *(float2*)&acc2[i][0];
            float2 p1 = *(float2*)&acc2[i][1];
            float2 p2 = *(float2*)&acc2[i][2];
            float2 p3 = *(float2*)&acc2[i][3];
            float* o = g_support + (size_t)gr * F_OUT + c0;
            *(float4*)(o)     = make_float4(p0.x, p0.y, p1.x, p1.y);
            *(float4*)(o + 4) = make_float4(p2.x, p2.y, p3.x, p3.y);
        }
    }
}

// ---------------------------------------------------------------------------
// Counting sort of edges by dst
// ---------------------------------------------------------------------------
__global__ void zero_counts_kernel(int n)
{
    int i = blockIdx.x * blockDim.x + threadIdx.x;
    if (i < n) g_cursor[i] = 0;
}

__global__ void hist_kernel(const int* __restrict__ dst, int E)
{
    int e = blockIdx.x * blockDim.x + threadIdx.x;
    if (e < E) atomicAdd(&g_cursor[dst[e]], 1);
}

// single-block exclusive scan of g_cursor[0..n) -> g_offsets, reset g_cursor=start
__global__ void scan_kernel(int n)
{
    __shared__ int bsum[1024];
    const int tid   = threadIdx.x;
    const int chunk = (n + 1023) / 1024;
    const int start = tid * chunk;
    const int end   = min(start + chunk, n);

    int s = 0;
    for (int i = start; i < end; i++) s += g_cursor[i];
    bsum[tid] = s;
    __syncthreads();

    // inclusive Hillis-Steele scan over 1024 partials
    for (int off = 1; off < 1024; off <<= 1) {
        int v = 0;
        if (tid >= off) v = bsum[tid - off];
        __syncthreads();
        if (tid >= off) bsum[tid] += v;
        __syncthreads();
    }
    int run = (tid == 0) ? 0 : bsum[tid - 1];
    for (int i = start; i < end; i++) {
        int c = g_cursor[i];
        g_offsets[i] = run;
        g_cursor[i]  = run;   // scatter cursor starts at row start
        run += c;
    }
}

__global__ void scatter_kernel(const int*   __restrict__ src,
                               const int*   __restrict__ dst,
                               const float* __restrict__ ew,
                               int E)
{
    int e = blockIdx.x * blockDim.x + threadIdx.x;
    if (e >= E) return;
    int d   = __ldg(dst + e);
    int pos = atomicAdd(&g_cursor[d], 1);
    g_sorted[pos] = make_int2(__ldg(src + e), __float_as_int(__ldg(ew + e)));
}

// ---------------------------------------------------------------------------
// Gather-accumulate: one warp per dst node; register accumulation, one write.
// After scatter, g_cursor[n] == row end. Bias folded in.
// ---------------------------------------------------------------------------
__global__ void gather_kernel(const float* __restrict__ bias,
                              float* __restrict__ out,
                              int n)
{
    int warp = (blockIdx.x * blockDim.x + threadIdx.x) >> 5;
    int lane = threadIdx.x & 31;
    if (warp >= n) return;

    const int beg = __ldg(g_offsets + warp);
    const int end = __ldg(g_cursor  + warp);

    float2 acc = make_float2(0.f, 0.f);
    int i = beg;
    // 2-deep unroll for memory-level parallelism
    for (; i + 2 <= end; i += 2) {
        int2 e0 = __ldg(&g_sorted[i]);
        int2 e1 = __ldg(&g_sorted[i + 1]);
        float2 v0 = *(const float2*)(g_support + (size_t)e0.x * F_OUT + lane * 2);
        float2 v1 = *(const float2*)(g_support + (size_t)e1.x * F_OUT + lane * 2);
        float w0 = __int_as_float(e0.y);
        float w1 = __int_as_float(e1.y);
        acc.x += v0.x * w0; acc.y += v0.y * w0;
        acc.x += v1.x * w1; acc.y += v1.y * w1;
    }
    if (i < end) {
        int2 e0 = __ldg(&g_sorted[i]);
        float2 v0 = *(const float2*)(g_support + (size_t)e0.x * F_OUT + lane * 2);
        float w0 = __int_as_float(e0.y);
        acc.x += v0.x * w0; acc.y += v0.y * w0;
    }

    float2 b = *(const float2*)(bias + lane * 2);
    *(float2*)(out + (size_t)warp * F_OUT + lane * 2) =
        make_float2(acc.x + b.x, acc.y + b.y);
}

// ---------------------------------------------------------------------------
extern "C" void kernel_launch(void* const* d_in, const int* in_sizes, int n_in,
                              void* d_out, int out_size)
{
    const float* x    = (const float*)d_in[0];   // [N, 128]
    const float* ew   = (const float*)d_in[1];   // [E]
    const float* W    = (const float*)d_in[2];   // [128, 64]
    const float* bias = (const float*)d_in[3];   // [64]
    const int*   src  = (const int*)  d_in[4];   // [E]
    const int*   dst  = (const int*)  d_in[5];   // [E]
    float*       out  = (float*)d_out;           // [N, 64]

    const int n = in_sizes[0] / F_IN;
    const int E = in_sizes[1];

    cudaFuncSetAttribute(gemm_support_kernel,
                         cudaFuncAttributeMaxDynamicSharedMemorySize, SMEM_BYTES);

    const int gemm_blocks = (n + TILE_M - 1) / TILE_M;
    gemm_support_kernel<<<gemm_blocks, GEMM_THREADS, SMEM_BYTES>>>(x, W, n);

    zero_counts_kernel<<<(n + 255) / 256, 256>>>(n);
    hist_kernel<<<(E + 255) / 256, 256>>>(dst, E);
    scan_kernel<<<1, 1024>>>(n);
    scatter_kernel<<<(E + 255) / 256, 256>>>(src, dst, ew, E);

    const long long gthreads = (long long)n * 32;
    gather_kernel<<<(int)((gthreads + 255) / 256), 256>>>(bias, out, n);
}

// round 8
// speedup vs baseline: 1.3721x; 1.3721x over previous
#include <cuda_runtime.h>
#include <cuda_bf16.h>

#define F_IN   128
#define F_OUT  64
#define N_NODES_MAX 100000
#define E_MAX       1600000

#define TILE_M        128
#define GEMM_THREADS  128
#define XS_STRIDE     129

#define SMEM_FLOATS   (TILE_M * XS_STRIDE + F_IN * F_OUT)
#define SMEM_BYTES    (SMEM_FLOATS * 4)

#define SCAN_BLK      1024
#define MAX_SCAN_BLKS 1024   // supports n up to 1M

// ---- device scratch (no allocations allowed) ----
__device__ float g_support[(size_t)N_NODES_MAX * F_OUT];   // 25.6 MB
__device__ int   g_offsets[N_NODES_MAX];                   // CSR row starts
__device__ int   g_cursor [N_NODES_MAX];                   // hist counts -> cursors -> row ends
__device__ int   g_bsums  [MAX_SCAN_BLKS];                 // scan block sums
__device__ int2  g_sorted [E_MAX];                         // {src, bits(ew)} sorted by dst

// packed f32x2 FMA (sm_100+; explicit 4-operand form avoids cicc ICE)
__device__ __forceinline__ void fma2(unsigned long long& d,
                                     unsigned long long a,
                                     unsigned long long b)
{
    unsigned long long r;
    asm volatile("fma.rn.f32x2 %0, %1, %2, %3;"
                 : "=l"(r) : "l"(a), "l"(b), "l"(d));
    d = r;
}
__device__ __forceinline__ unsigned long long pack2(float lo, float hi)
{
    unsigned long long r;
    asm("mov.b64 %0, {%1, %2};" : "=l"(r) : "f"(lo), "f"(hi));
    return r;
}

// ---------------------------------------------------------------------------
// Kernel 1: support = X @ W
// ---------------------------------------------------------------------------
__global__ void gemm_support_kernel(const float* __restrict__ X,
                                    const float* __restrict__ W,
                                    int n_rows)
{
    extern __shared__ float smem[];
    float* Xs = smem;
    float* Ws = smem + TILE_M * XS_STRIDE;

    const int tid      = threadIdx.x;
    const int row_base = blockIdx.x * TILE_M;

    {
        const float4* W4  = (const float4*)W;
        float4*       Ws4 = (float4*)Ws;
        #pragma unroll
        for (int i = 0; i < (F_IN * F_OUT / 4) / GEMM_THREADS; i++)
            Ws4[tid + i * GEMM_THREADS] = W4[tid + i * GEMM_THREADS];
    }

    #pragma unroll
    for (int i = 0; i < (TILE_M * F_IN / 4) / GEMM_THREADS; i++) {
        int idx = tid + i * GEMM_THREADS;
        int r   = idx >> 5;
        int kq  = idx & 31;
        float4 v = make_float4(0.f, 0.f, 0.f, 0.f);
        int gr = row_base + r;
        if (gr < n_rows)
            v = ((const float4*)(X + (size_t)gr * F_IN))[kq];
        float* dstp = &Xs[r * XS_STRIDE + kq * 4];
        dstp[0] = v.x; dstp[1] = v.y; dstp[2] = v.z; dstp[3] = v.w;
    }
    __syncthreads();

    const int tx = tid & 7;
    const int ty = tid >> 3;
    const int c0 = tx * 8;
    const int r0 = ty * 8;

    unsigned long long acc2[8][4];
    #pragma unroll
    for (int i = 0; i < 8; i++)
        #pragma unroll
        for (int j = 0; j < 4; j++)
            acc2[i][j] = 0ull;

    #pragma unroll 4
    for (int k = 0; k < F_IN; k++) {
        unsigned long long xv2[8];
        #pragma unroll
        for (int i = 0; i < 8; i++) {
            float xv = Xs[(r0 + i) * XS_STRIDE + k];
            xv2[i] = pack2(xv, xv);
        }
        const unsigned long long* wrow =
            (const unsigned long long*)&Ws[k * F_OUT + c0];
        unsigned long long wv2[4];
        #pragma unroll
        for (int j = 0; j < 4; j++) wv2[j] = wrow[j];

        #pragma unroll
        for (int i = 0; i < 8; i++)
            #pragma unroll
            for (int j = 0; j < 4; j++)
                fma2(acc2[i][j], xv2[i], wv2[j]);
    }

    #pragma unroll
    for (int i = 0; i < 8; i++) {
        int gr = row_base + r0 + i;
        if (gr < n_rows) {
            float2 p0 = *(float2*)&acc2[i][0];
            float2 p1 = *(float2*)&acc2[i][1];
            float2 p2 = *(float2*)&acc2[i][2];
            float2 p3 = *(float2*)&acc2[i][3];
            float* o = g_support + (size_t)gr * F_OUT + c0;
            *(float4*)(o)     = make_float4(p0.x, p0.y, p1.x, p1.y);
            *(float4*)(o + 4) = make_float4(p2.x, p2.y, p3.x, p3.y);
        }
    }
}

// ---------------------------------------------------------------------------
// Counting sort of edges by dst (multi-block scan)
// ---------------------------------------------------------------------------
__global__ void zero_counts_kernel(int n)
{
    int i = blockIdx.x * blockDim.x + threadIdx.x;
    if (i < n) g_cursor[i] = 0;
}

__global__ void hist_kernel(const int* __restrict__ dst, int E)
{
    int e = blockIdx.x * blockDim.x + threadIdx.x;
    if (e < E) atomicAdd(&g_cursor[dst[e]], 1);
}

// phase 1: per-block exclusive scan of 1024 counts; block total -> g_bsums
__global__ void __launch_bounds__(SCAN_BLK) scan_blocks_kernel(int n)
{
    __shared__ int sh[SCAN_BLK];
    const int tid = threadIdx.x;
    const int gid = blockIdx.x * SCAN_BLK + tid;

    int v = (gid < n) ? g_cursor[gid] : 0;
    sh[tid] = v;
    __syncthreads();

    #pragma unroll
    for (int off = 1; off < SCAN_BLK; off <<= 1) {
        int t = 0;
        if (tid >= off) t = sh[tid - off];
        __syncthreads();
        if (tid >= off) sh[tid] += t;
        __syncthreads();
    }

    if (gid < n) g_offsets[gid] = sh[tid] - v;   // block-local exclusive
    if (tid == SCAN_BLK - 1) g_bsums[blockIdx.x] = sh[tid];
}

// phase 2: single block scans the block sums (exclusive, in place)
__global__ void __launch_bounds__(MAX_SCAN_BLKS) scan_bsums_kernel(int nblocks)
{
    __shared__ int sh[MAX_SCAN_BLKS];
    const int tid = threadIdx.x;
    int v = (tid < nblocks) ? g_bsums[tid] : 0;
    sh[tid] = v;
    __syncthreads();

    #pragma unroll
    for (int off = 1; off < MAX_SCAN_BLKS; off <<= 1) {
        int t = 0;
        if (tid >= off) t = sh[tid - off];
        __syncthreads();
        if (tid >= off) sh[tid] += t;
        __syncthreads();
    }
    if (tid < nblocks) g_bsums[tid] = sh[tid] - v;   // exclusive
}

// phase 3: add block offset; init scatter cursor
__global__ void __launch_bounds__(SCAN_BLK) scan_add_kernel(int n)
{
    int gid = blockIdx.x * SCAN_BLK + threadIdx.x;
    if (gid < n) {
        int o = g_offsets[gid] + g_bsums[blockIdx.x];
        g_offsets[gid] = o;
        g_cursor[gid]  = o;
    }
}

__global__ void scatter_kernel(const int*   __restrict__ src,
                               const int*   __restrict__ dst,
                               const float* __restrict__ ew,
                               int E)
{
    int e = blockIdx.x * blockDim.x + threadIdx.x;
    if (e >= E) return;
    int d   = __ldg(dst + e);
    int pos = atomicAdd(&g_cursor[d], 1);
    g_sorted[pos] = make_int2(__ldg(src + e), __float_as_int(__ldg(ew + e)));
}

// ---------------------------------------------------------------------------
// Gather-accumulate: one warp per dst node; bias folded in.
// After scatter, g_cursor[i] == row end.
// ---------------------------------------------------------------------------
__global__ void gather_kernel(const float* __restrict__ bias,
                              float* __restrict__ out,
                              int n)
{
    int warp = (blockIdx.x * blockDim.x + threadIdx.x) >> 5;
    int lane = threadIdx.x & 31;
    if (warp >= n) return;

    const int beg = __ldg(g_offsets + warp);
    const int end = __ldg(g_cursor  + warp);

    float2 acc = make_float2(0.f, 0.f);
    int i = beg;
    // 4-deep for MLP
    for (; i + 4 <= end; i += 4) {
        int2 e0 = __ldg(&g_sorted[i]);
        int2 e1 = __ldg(&g_sorted[i + 1]);
        int2 e2 = __ldg(&g_sorted[i + 2]);
        int2 e3 = __ldg(&g_sorted[i + 3]);
        float2 v0 = *(const float2*)(g_support + (size_t)e0.x * F_OUT + lane * 2);
        float2 v1 = *(const float2*)(g_support + (size_t)e1.x * F_OUT + lane * 2);
        float2 v2 = *(const float2*)(g_support + (size_t)e2.x * F_OUT + lane * 2);
        float2 v3 = *(const float2*)(g_support + (size_t)e3.x * F_OUT + lane * 2);
        float w0 = __int_as_float(e0.y);
        float w1 = __int_as_float(e1.y);
        float w2 = __int_as_float(e2.y);
        float w3 = __int_as_float(e3.y);
        acc.x += v0.x * w0; acc.y += v0.y * w0;
        acc.x += v1.x * w1; acc.y += v1.y * w1;
        acc.x += v2.x * w2; acc.y += v2.y * w2;
        acc.x += v3.x * w3; acc.y += v3.y * w3;
    }
    for (; i < end; i++) {
        int2 e0 = __ldg(&g_sorted[i]);
        float2 v0 = *(const float2*)(g_support + (size_t)e0.x * F_OUT + lane * 2);
        float w0 = __int_as_float(e0.y);
        acc.x += v0.x * w0; acc.y += v0.y * w0;
    }

    float2 b = *(const float2*)(bias + lane * 2);
    *(float2*)(out + (size_t)warp * F_OUT + lane * 2) =
        make_float2(acc.x + b.x, acc.y + b.y);
}

// ---------------------------------------------------------------------------
extern "C" void kernel_launch(void* const* d_in, const int* in_sizes, int n_in,
                              void* d_out, int out_size)
{
    const float* x    = (const float*)d_in[0];   // [N, 128]
    const float* ew   = (const float*)d_in[1];   // [E]
    const float* W    = (const float*)d_in[2];   // [128, 64]
    const float* bias = (const float*)d_in[3];   // [64]
    const int*   src  = (const int*)  d_in[4];   // [E]
    const int*   dst  = (const int*)  d_in[5];   // [E]
    float*       out  = (float*)d_out;           // [N, 64]

    const int n = in_sizes[0] / F_IN;
    const int E = in_sizes[1];

    cudaFuncSetAttribute(gemm_support_kernel,
                         cudaFuncAttributeMaxDynamicSharedMemorySize, SMEM_BYTES);

    const int gemm_blocks = (n + TILE_M - 1) / TILE_M;
    gemm_support_kernel<<<gemm_blocks, GEMM_THREADS, SMEM_BYTES>>>(x, W, n);

    const int scan_blocks = (n + SCAN_BLK - 1) / SCAN_BLK;

    zero_counts_kernel<<<(n + 255) / 256, 256>>>(n);
    hist_kernel<<<(E + 255) / 256, 256>>>(dst, E);
    scan_blocks_kernel<<<scan_blocks, SCAN_BLK>>>(n);
    scan_bsums_kernel<<<1, MAX_SCAN_BLKS>>>(scan_blocks);
    scan_add_kernel<<<scan_blocks, SCAN_BLK>>>(n);
    scatter_kernel<<<(E + 255) / 256, 256>>>(src, dst, ew, E);

    const long long gthreads = (long long)n * 32;
    gather_kernel<<<(int)((gthreads + 255) / 256), 256>>>(bias, out, n);
}

// round 9
// speedup vs baseline: 1.8841x; 1.3732x over previous
#include <cuda_runtime.h>
#include <cuda_bf16.h>

#define F_IN   128
#define F_OUT  64
#define N_NODES_MAX 100000

#define TILE_M        128
#define GEMM_THREADS  128
#define XS_STRIDE     129   // pad to kill bank conflicts on Xs[row][k] reads

#define SMEM_FLOATS   (TILE_M * XS_STRIDE + F_IN * F_OUT)
#define SMEM_BYTES    (SMEM_FLOATS * 4)

// scratch for support = X @ W  (25.6 MB)
__device__ float g_support[(size_t)N_NODES_MAX * F_OUT];

// packed f32x2 FMA (sm_100+; explicit 4-operand form avoids cicc ICE)
__device__ __forceinline__ void fma2(unsigned long long& d,
                                     unsigned long long a,
                                     unsigned long long b)
{
    unsigned long long r;
    asm volatile("fma.rn.f32x2 %0, %1, %2, %3;"
                 : "=l"(r) : "l"(a), "l"(b), "l"(d));
    d = r;
}
__device__ __forceinline__ unsigned long long pack2(float lo, float hi)
{
    unsigned long long r;
    asm("mov.b64 %0, {%1, %2};" : "=l"(r) : "f"(lo), "f"(hi));
    return r;
}

// ---------------------------------------------------------------------------
// Kernel 1: support = X @ W   (128x64 tile / 128 threads; 8x8 per thread,
// accumulators packed pairwise -> fma.rn.f32x2)
// ---------------------------------------------------------------------------
__global__ void gemm_support_kernel(const float* __restrict__ X,
                                    const float* __restrict__ W,
                                    int n_rows)
{
    extern __shared__ float smem[];
    float* Xs = smem;                          // [TILE_M][XS_STRIDE]
    float* Ws = smem + TILE_M * XS_STRIDE;     // [F_IN][F_OUT] row-major

    const int tid      = threadIdx.x;
    const int row_base = blockIdx.x * TILE_M;

    // stage W (8192 floats = 2048 float4)
    {
        const float4* W4  = (const float4*)W;
        float4*       Ws4 = (float4*)Ws;
        #pragma unroll
        for (int i = 0; i < (F_IN * F_OUT / 4) / GEMM_THREADS; i++)
            Ws4[tid + i * GEMM_THREADS] = W4[tid + i * GEMM_THREADS];
    }

    // stage X tile
    #pragma unroll
    for (int i = 0; i < (TILE_M * F_IN / 4) / GEMM_THREADS; i++) {
        int idx = tid + i * GEMM_THREADS;
        int r   = idx >> 5;
        int kq  = idx & 31;
        float4 v = make_float4(0.f, 0.f, 0.f, 0.f);
        int gr = row_base + r;
        if (gr < n_rows)
            v = ((const float4*)(X + (size_t)gr * F_IN))[kq];
        float* dstp = &Xs[r * XS_STRIDE + kq * 4];
        dstp[0] = v.x; dstp[1] = v.y; dstp[2] = v.z; dstp[3] = v.w;
    }
    __syncthreads();

    const int tx = tid & 7;
    const int ty = tid >> 3;
    const int c0 = tx * 8;
    const int r0 = ty * 8;

    unsigned long long acc2[8][4];
    #pragma unroll
    for (int i = 0; i < 8; i++)
        #pragma unroll
        for (int j = 0; j < 4; j++)
            acc2[i][j] = 0ull;

    #pragma unroll 4
    for (int k = 0; k < F_IN; k++) {
        unsigned long long xv2[8];
        #pragma unroll
        for (int i = 0; i < 8; i++) {
            float xv = Xs[(r0 + i) * XS_STRIDE + k];
            xv2[i] = pack2(xv, xv);
        }
        const unsigned long long* wrow =
            (const unsigned long long*)&Ws[k * F_OUT + c0];
        unsigned long long wv2[4];
        #pragma unroll
        for (int j = 0; j < 4; j++) wv2[j] = wrow[j];

        #pragma unroll
        for (int i = 0; i < 8; i++)
            #pragma unroll
            for (int j = 0; j < 4; j++)
                fma2(acc2[i][j], xv2[i], wv2[j]);
    }

    #pragma unroll
    for (int i = 0; i < 8; i++) {
        int gr = row_base + r0 + i;
        if (gr < n_rows) {
            float2 p0 = *(float2*)&acc2[i][0];
            float2 p1 = *(float2*)&acc2[i][1];
            float2 p2 = *(float2*)&acc2[i][2];
            float2 p3 = *(float2*)&acc2[i][3];
            float* o = g_support + (size_t)gr * F_OUT + c0;
            *(float4*)(o)     = make_float4(p0.x, p0.y, p1.x, p1.y);
            *(float4*)(o + 4) = make_float4(p2.x, p2.y, p3.x, p3.y);
        }
    }
}

// ---------------------------------------------------------------------------
// Kernel 2: out[i][c] = bias[c]
// ---------------------------------------------------------------------------
__global__ void init_out_kernel(float* __restrict__ out,
                                const float* __restrict__ bias,
                                int total)
{
    int i = blockIdx.x * blockDim.x + threadIdx.x;
    if (i < total)
        out[i] = __ldg(bias + (i & (F_OUT - 1)));
}

// ---------------------------------------------------------------------------
// Kernel 3: COO SPMM scatter-add. 16 threads per edge, float4 lanes,
// vectorized global reduction (red.global.add.v4.f32, no return trip).
// Each thread handles TWO independent edges (e and e+half) for MLP.
// ---------------------------------------------------------------------------
__global__ void spmm_scatter_kernel(const float* __restrict__ ew,
                                    const int*  __restrict__ src,
                                    const int*  __restrict__ dst,
                                    float* __restrict__ out,
                                    int E, int half)
{
    long long t = (long long)blockIdx.x * blockDim.x + threadIdx.x;
    int e0 = (int)(t >> 4);
    int q  = (int)(t & 15);
    if (e0 >= half) return;
    int e1 = e0 + half;
    bool has1 = (e1 < E);

    // edge metadata (broadcast across the 16-lane group)
    int   s0 = __ldg(src + e0);
    int   d0 = __ldg(dst + e0);
    float w0 = __ldg(ew  + e0);
    int   s1 = 0, d1 = 0;
    float w1 = 0.f;
    if (has1) {
        s1 = __ldg(src + e1);
        d1 = __ldg(dst + e1);
        w1 = __ldg(ew  + e1);
    }

    // two independent support reads in flight
    const float4 v0 = *(const float4*)(g_support + (size_t)s0 * F_OUT + q * 4);
    float4 v1 = make_float4(0.f, 0.f, 0.f, 0.f);
    if (has1)
        v1 = *(const float4*)(g_support + (size_t)s1 * F_OUT + q * 4);

    {
        float* p = out + (size_t)d0 * F_OUT + q * 4;
        float m0 = v0.x * w0, m1 = v0.y * w0, m2 = v0.z * w0, m3 = v0.w * w0;
        asm volatile("red.global.add.v4.f32 [%0], {%1, %2, %3, %4};"
                     :: "l"(p), "f"(m0), "f"(m1), "f"(m2), "f"(m3)
                     : "memory");
    }
    if (has1) {
        float* p = out + (size_t)d1 * F_OUT + q * 4;
        float m0 = v1.x * w1, m1 = v1.y * w1, m2 = v1.z * w1, m3 = v1.w * w1;
        asm volatile("red.global.add.v4.f32 [%0], {%1, %2, %3, %4};"
                     :: "l"(p), "f"(m0), "f"(m1), "f"(m2), "f"(m3)
                     : "memory");
    }
}

// ---------------------------------------------------------------------------
extern "C" void kernel_launch(void* const* d_in, const int* in_sizes, int n_in,
                              void* d_out, int out_size)
{
    const float* x    = (const float*)d_in[0];   // [N, 128]
    const float* ew   = (const float*)d_in[1];   // [E]
    const float* W    = (const float*)d_in[2];   // [128, 64]
    const float* bias = (const float*)d_in[3];   // [64]
    const int*   src  = (const int*)  d_in[4];   // [E]
    const int*   dst  = (const int*)  d_in[5];   // [E]
    float*       out  = (float*)d_out;           // [N, 64]

    const int n = in_sizes[0] / F_IN;
    const int E = in_sizes[1];

    cudaFuncSetAttribute(gemm_support_kernel,
                         cudaFuncAttributeMaxDynamicSharedMemorySize, SMEM_BYTES);

    const int gemm_blocks = (n + TILE_M - 1) / TILE_M;
    gemm_support_kernel<<<gemm_blocks, GEMM_THREADS, SMEM_BYTES>>>(x, W, n);

    const int total = n * F_OUT;
    init_out_kernel<<<(total + 255) / 256, 256>>>(out, bias, total);

    const int half = (E + 1) / 2;
    const long long spmm_threads = (long long)half * 16;
    const int spmm_blocks = (int)((spmm_threads + 255) / 256);
    spmm_scatter_kernel<<<spmm_blocks, 256>>>(ew, src, dst, out, E, half);
}